// round 15
// baseline (speedup 1.0000x reference)
#include <cuda_runtime.h>
#include <math.h>
#include <float.h>

#define HH 496
#define WW 496
#define NC 9          // sigma x lambda combos
#define NT 8          // thetas
#define NW 31         // windows per dim (496/16)
#define NWIN (NW*NW)  // 961
#define NCOEF (NT*NC*25)
#define NFILT (NT*NC)

// ---- scratch (static device globals; no allocation) ----
__device__ float gCoef[NCOEF];                // [t][c][25] dense
__device__ float gOut[NC*HH*WW];              // conv+max result, 8.86 MB
__device__ float gPartial[NC*NWIN];           // per-window channel sums
__device__ float gMaxVal[NC*NWIN];            // per-window channel max
__device__ int   gMaxIdx[NC*NWIN];            // first index of max (0..255)
__device__ float gThr5[NC];                   // mean*5 per channel
__device__ int   gValid[NWIN];                // bit0: valid, bit1: needs exact rescan

__device__ __constant__ float dThetas[8] = {
    0.39269908169872414f, 0.7853981633974483f, 1.1780972450961724f,
    1.5707963267948966f,  1.9634954084936207f, 2.356194490192345f,
    2.748893571891069f,   3.141592653589793f
};

// ============ Kernel 1: Gabor bank ============
__global__ void gabor_kernel(const float* __restrict__ sigmas,
                             const float* __restrict__ lambdas) {
    int i = blockIdx.x * blockDim.x + threadIdx.x;
    if (i >= NCOEF) return;
    int k = i % 25;
    int c = (i / 25) % NC;
    int t = i / (25 * NC);
    int s = c / 3, l = c % 3;
    float sig = sigmas[s];
    float lam = lambdas[l];
    float th  = dThetas[t];
    int ky = k / 5, kx = k % 5;
    float y = (float)ky - 2.0f;
    float x = (float)kx - 2.0f;
    float st = sinf(th), ct = cosf(th);
    float yth = -x * st + y * ct;
    float xth =  x * ct + y * st;
    float sx = sig;          // sigma_x
    float sy = 2.0f * sig;   // sigma_y = sigma/gamma, gamma=0.5
    float e = expf(-0.5f * (xth*xth/(sx*sx) + yth*yth/(sy*sy)));
    float g = e * cosf(6.283185307179586f * xth / lam + 1.5707963267948966f);
    gCoef[(t * NC + c) * 25 + k] = g;
}

// ============ Kernel 2: conv (scalar FFMA, proven) + fused window stats =====
// 31x31 blocks of 64 threads; 16x16 output tile == one detection window.
// Thread = 4 horizontal pixels; per coefficient 1 smem load feeds 4 FMAs.
// Coefficient rows padded to 28 floats (112B) so taps load as LDS.128 x6 + 1.
__global__ void __launch_bounds__(64)
conv_kernel(const float* __restrict__ img) {
    __shared__ float sIn[20 * 20];
    __shared__ float sCf[NFILT * 28];   // padded: row f at 28*f, 16B-aligned
    __shared__ float sVal[NC][2];
    __shared__ int   sIdx[NC][2];
    __shared__ float sSum[NC][2];

    int tid = threadIdx.x;
    int bx = blockIdx.x, by = blockIdx.y;
    int r0 = by * 16 - 2, c0 = bx * 16 - 2;

    // reset validity accumulator for this window (graph replays stay pure)
    if (tid == 32) gValid[by * NW + bx] = 0;

    // halo'd input tile (zero pad)
    for (int i = tid; i < 400; i += 64) {
        int r = i / 20, cc = i % 20;
        int gr = r0 + r, gc = c0 + cc;
        sIn[i] = (gr >= 0 && gr < HH && gc >= 0 && gc < WW) ? img[gr * WW + gc] : 0.0f;
    }
    // coefficients -> padded smem rows
    for (int i = tid; i < NCOEF; i += 64) {
        int f = i / 25, k = i % 25;
        sCf[f * 28 + k] = gCoef[i];
    }
    __syncthreads();

    int ty = tid >> 2;            // 0..15
    int tx = (tid & 3) * 4;       // 0,4,8,12

    float vin[5][8];
    #pragma unroll
    for (int r = 0; r < 5; r++)
        #pragma unroll
        for (int cc = 0; cc < 8; cc++)
            vin[r][cc] = sIn[(ty + r) * 20 + tx + cc];

    float vmax[4][NC];
    #pragma unroll
    for (int p = 0; p < 4; p++)
        #pragma unroll
        for (int c = 0; c < NC; c++) vmax[p][c] = -FLT_MAX;

#define TAP(wv, kk) { const int ky = (kk) / 5, kx = (kk) % 5;                 \
        a0 = fmaf((wv), vin[ky][kx + 0], a0);                                 \
        a1 = fmaf((wv), vin[ky][kx + 1], a1);                                 \
        a2 = fmaf((wv), vin[ky][kx + 2], a2);                                 \
        a3 = fmaf((wv), vin[ky][kx + 3], a3); }

    for (int t = 0; t < NT; t++) {
        #pragma unroll
        for (int c = 0; c < NC; c++) {
            const float* cf = sCf + (t * NC + c) * 28;
            const float4* cf4 = (const float4*)cf;
            float a0 = 0.0f, a1 = 0.0f, a2 = 0.0f, a3 = 0.0f;
            #pragma unroll
            for (int q = 0; q < 6; q++) {
                float4 w = cf4[q];
                TAP(w.x, 4 * q + 0)
                TAP(w.y, 4 * q + 1)
                TAP(w.z, 4 * q + 2)
                TAP(w.w, 4 * q + 3)
            }
            float w24 = cf[24];
            TAP(w24, 24)
            vmax[0][c] = fmaxf(vmax[0][c], a0);
            vmax[1][c] = fmaxf(vmax[1][c], a1);
            vmax[2][c] = fmaxf(vmax[2][c], a2);
            vmax[3][c] = fmaxf(vmax[3][c], a3);
        }
    }
#undef TAP

    // global stores
    int gy = by * 16 + ty;
    int gx = bx * 16 + tx;
    #pragma unroll
    for (int c = 0; c < NC; c++) {
        float4 o = make_float4(vmax[0][c], vmax[1][c], vmax[2][c], vmax[3][c]);
        *(float4*)&gOut[c * HH * WW + gy * WW + gx] = o;
    }

    // fused per-window stats. Flat index within 16x16 for element e of this
    // thread is exactly f = 4*tid + e (ascending), so first-occurrence
    // argmax = min-index tie-breaking across lanes.
    int lane = tid & 31, wid = tid >> 5;
    #pragma unroll
    for (int c = 0; c < NC; c++) {
        float best = vmax[0][c]; int bidx = 4 * tid;
        if (vmax[1][c] > best) { best = vmax[1][c]; bidx = 4 * tid + 1; }
        if (vmax[2][c] > best) { best = vmax[2][c]; bidx = 4 * tid + 2; }
        if (vmax[3][c] > best) { best = vmax[3][c]; bidx = 4 * tid + 3; }
        float s = vmax[0][c] + vmax[1][c] + vmax[2][c] + vmax[3][c];
        #pragma unroll
        for (int off = 16; off; off >>= 1) {
            s += __shfl_xor_sync(0xffffffffu, s, off);
            float ov = __shfl_xor_sync(0xffffffffu, best, off);
            int   oi = __shfl_xor_sync(0xffffffffu, bidx, off);
            if (ov > best || (ov == best && oi < bidx)) { best = ov; bidx = oi; }
        }
        if (lane == 0) { sVal[c][wid] = best; sIdx[c][wid] = bidx; sSum[c][wid] = s; }
    }
    __syncthreads();
    if (tid < NC) {
        float best = sVal[tid][0]; int bidx = sIdx[tid][0];
        float s = sSum[tid][0] + sSum[tid][1];
        float ov = sVal[tid][1]; int oi = sIdx[tid][1];
        if (ov > best || (ov == best && oi < bidx)) { best = ov; bidx = oi; }
        int b = by * NW + bx;
        gPartial[tid * NWIN + b] = s;
        gMaxVal[tid * NWIN + b]  = best;
        gMaxIdx[tid * NWIN + b]  = bidx;
    }
}

// ============ Kernel 3: mean -> thr5, then per-window validity bits =========
// One block per channel. Phase 1: deterministic sum -> thr. Phase 2: scan this
// channel's contiguous gMaxVal/gMaxIdx and atomicOr validity bits into gValid
// (bitwise OR is order-independent -> deterministic).
//  M <= thr          -> contributes nothing
//  M >  thr, M > 0   -> bit0 if first index of max == 128
//  M >  thr, M <= 0  -> bit1 (patch does exact rescan; measure-zero case)
__global__ void mean_kernel() {
    __shared__ float sh[128];
    __shared__ float sThr;
    int c = blockIdx.x;
    int tid = threadIdx.x;
    float s = 0.0f;
    for (int i = tid; i < NWIN; i += 128) s += gPartial[c * NWIN + i];
    sh[tid] = s;
    __syncthreads();
    if (tid < 64) sh[tid] += sh[tid + 64];
    __syncthreads();
    if (tid < 32) {
        s = sh[tid] + sh[tid + 32];
        #pragma unroll
        for (int off = 16; off; off >>= 1)
            s += __shfl_down_sync(0xffffffffu, s, off);
        if (tid == 0) {
            float thr = (s / (float)(HH * WW)) * 5.0f;
            gThr5[c] = thr;
            sThr = thr;
        }
    }
    __syncthreads();
    float thr = sThr;
    for (int i = tid; i < NWIN; i += 128) {
        float M  = gMaxVal[c * NWIN + i];
        int   id = gMaxIdx[c * NWIN + i];
        if (M > thr) {
            int bits = (M > 0.0f) ? ((id == 128) ? 1 : 0) : 2;
            if (bits) atomicOr(&gValid[i], bits);
        }
    }
}

// ============ Kernel 4: patches, one block per window (all 9 channels) ======
// 961 blocks x 256 threads. Pass 1 reads all channels (L2-hot) building a
// 9-bit per-channel nonzero mask (__reduce_or_sync + one barrier). Pass 2
// reloads and stores masked. Validity is a single gValid[w] load; bit1
// triggers the exact cooperative rescan (block-uniform, essentially never).
__global__ void __launch_bounds__(256)
patch_kernel(float* __restrict__ dst) {
    __shared__ unsigned sW[8];
    __shared__ float sRv[NC][8];
    __shared__ int   sRi[NC][8];
    __shared__ int   sValid;

    int w = blockIdx.x;
    int tid = threadIdx.x;
    int lane = tid & 31, wid = tid >> 5;
    int wr = (w / NW) * 16 - 8;    // top row of 32x32 patch in image coords
    int wc = (w % NW) * 16 - 8;
    int i  = tid >> 3;             // patch row 0..31
    int j0 = (tid & 7) * 4;        // patch col base
    int rr = wr + i;
    bool interior = (wr >= 0) & (wr + 31 < HH) & (wc >= 0) & (wc + 31 < WW);
    bool rok = (rr >= 0 && rr < HH);

    int vf = gValid[w];
    int valid;
    if (vf & 2) {                  // exact rescan, block-uniform, rare
        int R = (w / NW) * 16, C = (w % NW) * 16;
        int fi = tid >> 4, fj = tid & 15;          // f == tid, ascending
        for (int ch = 0; ch < NC; ch++) {
            float thr = gThr5[ch];
            float v = gOut[ch * HH * WW + (R + fi) * WW + C + fj];
            float best = (v > thr) ? v : 0.0f;
            int bidx = tid;
            #pragma unroll
            for (int off = 16; off; off >>= 1) {
                float ov = __shfl_xor_sync(0xffffffffu, best, off);
                int   oi = __shfl_xor_sync(0xffffffffu, bidx, off);
                if (ov > best || (ov == best && oi < bidx)) { best = ov; bidx = oi; }
            }
            if (lane == 0) { sRv[ch][wid] = best; sRi[ch][wid] = bidx; }
        }
        __syncthreads();
        if (tid == 0) {
            int vv = 0;
            for (int ch = 0; ch < NC; ch++) {
                float best = sRv[ch][0]; int bidx = sRi[ch][0];
                for (int k = 1; k < 8; k++) {
                    float ov = sRv[ch][k]; int oi = sRi[ch][k];
                    if (ov > best || (ov == best && oi < bidx)) { best = ov; bidx = oi; }
                }
                vv |= (bidx == 128);
            }
            sValid = vv;
        }
        __syncthreads();
        valid = sValid;
    } else {
        valid = vf & 1;
    }

    // ---- pass 1: per-channel any-nonzero mask ----
    unsigned nzm = 0;
    if (interior) {
        const float* base = gOut + rr * WW + wc + j0;
        #pragma unroll
        for (int c = 0; c < NC; c++) {
            float4 v = *(const float4*)(base + c * HH * WW);
            if ((v.x != 0.0f) | (v.y != 0.0f) | (v.z != 0.0f) | (v.w != 0.0f))
                nzm |= 1u << c;
        }
    } else {
        #pragma unroll
        for (int c = 0; c < NC; c++) {
            const float* o = gOut + c * HH * WW;
            bool nz = false;
            #pragma unroll
            for (int e = 0; e < 4; e++) {
                int cc = wc + j0 + e;
                float t = (rok && cc >= 0 && cc < WW) ? o[rr * WW + cc] : 0.0f;
                nz |= (t != 0.0f);
            }
            if (nz) nzm |= 1u << c;
        }
    }
    unsigned wm = __reduce_or_sync(0xffffffffu, nzm);
    if (lane == 0) sW[wid] = wm;
    __syncthreads();
    unsigned blockmask = 0;
    #pragma unroll
    for (int k = 0; k < 8; k++) blockmask |= sW[k];
    if (!valid) blockmask = 0;

    // ---- pass 2: reload + masked store ----
    if (interior) {
        const float* base = gOut + rr * WW + wc + j0;
        #pragma unroll
        for (int c = 0; c < NC; c++) {
            float m = ((blockmask >> c) & 1u) ? 1.0f : 0.0f;
            float4 v = *(const float4*)(base + c * HH * WW);
            float4 ov = make_float4(v.x * m, v.y * m, v.z * m, v.w * m);
            ((float4*)dst)[(c * NWIN + w) * 256 + tid] = ov;
        }
    } else {
        #pragma unroll
        for (int c = 0; c < NC; c++) {
            float m = ((blockmask >> c) & 1u) ? 1.0f : 0.0f;
            const float* o = gOut + c * HH * WW;
            float t[4];
            #pragma unroll
            for (int e = 0; e < 4; e++) {
                int cc = wc + j0 + e;
                t[e] = (rok && cc >= 0 && cc < WW) ? o[rr * WW + cc] : 0.0f;
            }
            float4 ov = make_float4(t[0] * m, t[1] * m, t[2] * m, t[3] * m);
            ((float4*)dst)[(c * NWIN + w) * 256 + tid] = ov;
        }
    }
}

// ============ launcher ============
extern "C" void kernel_launch(void* const* d_in, const int* in_sizes, int n_in,
                              void* d_out, int out_size) {
    const float* img     = (const float*)d_in[0];
    const float* sigmas  = (const float*)d_in[1];
    const float* lambdas = (const float*)d_in[2];
    float* out = (float*)d_out;

    gabor_kernel<<<(NCOEF + 255) / 256, 256>>>(sigmas, lambdas);
    conv_kernel<<<dim3(NW, NW), 64>>>(img);
    mean_kernel<<<NC, 128>>>();
    patch_kernel<<<NWIN, 256>>>(out);
}

// round 16
// speedup vs baseline: 1.0543x; 1.0543x over previous
#include <cuda_runtime.h>
#include <math.h>
#include <float.h>

#define HH 496
#define WW 496
#define NC 9          // sigma x lambda combos
#define NT 8          // thetas
#define NW 31         // windows per dim (496/16)
#define NWIN (NW*NW)  // 961
#define NCOEF (NT*NC*25)
#define NFILT (NT*NC)

// ---- scratch (static device globals; no allocation) ----
__device__ float gCoef[NCOEF];                // [t][c][25] dense
__device__ float gOut[NC*HH*WW];              // conv+max result, 8.86 MB
__device__ float gPartial[NC*NWIN];           // per-window channel sums
__device__ float gMaxVal[NC*NWIN];            // per-window channel max
__device__ int   gMaxIdx[NC*NWIN];            // first index of max (0..255)
__device__ float gThr5[NC];                   // mean*5 per channel
__device__ int   gValid[NWIN];                // bit0: valid, bit1: needs exact rescan

__device__ __constant__ float dThetas[8] = {
    0.39269908169872414f, 0.7853981633974483f, 1.1780972450961724f,
    1.5707963267948966f,  1.9634954084936207f, 2.356194490192345f,
    2.748893571891069f,   3.141592653589793f
};

// ============ Kernel 1: Gabor bank ============
__global__ void gabor_kernel(const float* __restrict__ sigmas,
                             const float* __restrict__ lambdas) {
    int i = blockIdx.x * blockDim.x + threadIdx.x;
    if (i >= NCOEF) return;
    int k = i % 25;
    int c = (i / 25) % NC;
    int t = i / (25 * NC);
    int s = c / 3, l = c % 3;
    float sig = sigmas[s];
    float lam = lambdas[l];
    float th  = dThetas[t];
    int ky = k / 5, kx = k % 5;
    float y = (float)ky - 2.0f;
    float x = (float)kx - 2.0f;
    float st = sinf(th), ct = cosf(th);
    float yth = -x * st + y * ct;
    float xth =  x * ct + y * st;
    float sx = sig;          // sigma_x
    float sy = 2.0f * sig;   // sigma_y = sigma/gamma, gamma=0.5
    float e = expf(-0.5f * (xth*xth/(sx*sx) + yth*yth/(sy*sy)));
    float g = e * cosf(6.283185307179586f * xth / lam + 1.5707963267948966f);
    gCoef[(t * NC + c) * 25 + k] = g;
}

// ============ Kernel 2: conv (scalar FFMA, proven) + fused window stats =====
// 31x31 blocks of 64 threads; 16x16 output tile == one detection window.
// Thread = 4 horizontal pixels; per coefficient 1 smem load feeds 4 FMAs.
// Coefficient rows padded to 28 floats (112B) so taps load as LDS.128 x6 + 1.
__global__ void __launch_bounds__(64)
conv_kernel(const float* __restrict__ img) {
    __shared__ float sIn[20 * 20];
    __shared__ float sCf[NFILT * 28];   // padded: row f at 28*f, 16B-aligned
    __shared__ float sVal[NC][2];
    __shared__ int   sIdx[NC][2];
    __shared__ float sSum[NC][2];

    int tid = threadIdx.x;
    int bx = blockIdx.x, by = blockIdx.y;
    int r0 = by * 16 - 2, c0 = bx * 16 - 2;

    // reset validity accumulator for this window (graph replays stay pure)
    if (tid == 32) gValid[by * NW + bx] = 0;

    // halo'd input tile (zero pad)
    for (int i = tid; i < 400; i += 64) {
        int r = i / 20, cc = i % 20;
        int gr = r0 + r, gc = c0 + cc;
        sIn[i] = (gr >= 0 && gr < HH && gc >= 0 && gc < WW) ? img[gr * WW + gc] : 0.0f;
    }
    // coefficients -> padded smem rows
    for (int i = tid; i < NCOEF; i += 64) {
        int f = i / 25, k = i % 25;
        sCf[f * 28 + k] = gCoef[i];
    }
    __syncthreads();

    int ty = tid >> 2;            // 0..15
    int tx = (tid & 3) * 4;       // 0,4,8,12

    float vin[5][8];
    #pragma unroll
    for (int r = 0; r < 5; r++)
        #pragma unroll
        for (int cc = 0; cc < 8; cc++)
            vin[r][cc] = sIn[(ty + r) * 20 + tx + cc];

    float vmax[4][NC];
    #pragma unroll
    for (int p = 0; p < 4; p++)
        #pragma unroll
        for (int c = 0; c < NC; c++) vmax[p][c] = -FLT_MAX;

#define TAP(wv, kk) { const int ky = (kk) / 5, kx = (kk) % 5;                 \
        a0 = fmaf((wv), vin[ky][kx + 0], a0);                                 \
        a1 = fmaf((wv), vin[ky][kx + 1], a1);                                 \
        a2 = fmaf((wv), vin[ky][kx + 2], a2);                                 \
        a3 = fmaf((wv), vin[ky][kx + 3], a3); }

    for (int t = 0; t < NT; t++) {
        #pragma unroll
        for (int c = 0; c < NC; c++) {
            const float* cf = sCf + (t * NC + c) * 28;
            const float4* cf4 = (const float4*)cf;
            float a0 = 0.0f, a1 = 0.0f, a2 = 0.0f, a3 = 0.0f;
            #pragma unroll
            for (int q = 0; q < 6; q++) {
                float4 w = cf4[q];
                TAP(w.x, 4 * q + 0)
                TAP(w.y, 4 * q + 1)
                TAP(w.z, 4 * q + 2)
                TAP(w.w, 4 * q + 3)
            }
            float w24 = cf[24];
            TAP(w24, 24)
            vmax[0][c] = fmaxf(vmax[0][c], a0);
            vmax[1][c] = fmaxf(vmax[1][c], a1);
            vmax[2][c] = fmaxf(vmax[2][c], a2);
            vmax[3][c] = fmaxf(vmax[3][c], a3);
        }
    }
#undef TAP

    // global stores
    int gy = by * 16 + ty;
    int gx = bx * 16 + tx;
    #pragma unroll
    for (int c = 0; c < NC; c++) {
        float4 o = make_float4(vmax[0][c], vmax[1][c], vmax[2][c], vmax[3][c]);
        *(float4*)&gOut[c * HH * WW + gy * WW + gx] = o;
    }

    // fused per-window stats. Flat index within 16x16 for element e of this
    // thread is exactly f = 4*tid + e (ascending), so first-occurrence
    // argmax = min-index tie-breaking across lanes.
    int lane = tid & 31, wid = tid >> 5;
    #pragma unroll
    for (int c = 0; c < NC; c++) {
        float best = vmax[0][c]; int bidx = 4 * tid;
        if (vmax[1][c] > best) { best = vmax[1][c]; bidx = 4 * tid + 1; }
        if (vmax[2][c] > best) { best = vmax[2][c]; bidx = 4 * tid + 2; }
        if (vmax[3][c] > best) { best = vmax[3][c]; bidx = 4 * tid + 3; }
        float s = vmax[0][c] + vmax[1][c] + vmax[2][c] + vmax[3][c];
        #pragma unroll
        for (int off = 16; off; off >>= 1) {
            s += __shfl_xor_sync(0xffffffffu, s, off);
            float ov = __shfl_xor_sync(0xffffffffu, best, off);
            int   oi = __shfl_xor_sync(0xffffffffu, bidx, off);
            if (ov > best || (ov == best && oi < bidx)) { best = ov; bidx = oi; }
        }
        if (lane == 0) { sVal[c][wid] = best; sIdx[c][wid] = bidx; sSum[c][wid] = s; }
    }
    __syncthreads();
    if (tid < NC) {
        float best = sVal[tid][0]; int bidx = sIdx[tid][0];
        float s = sSum[tid][0] + sSum[tid][1];
        float ov = sVal[tid][1]; int oi = sIdx[tid][1];
        if (ov > best || (ov == best && oi < bidx)) { best = ov; bidx = oi; }
        int b = by * NW + bx;
        gPartial[tid * NWIN + b] = s;
        gMaxVal[tid * NWIN + b]  = best;
        gMaxIdx[tid * NWIN + b]  = bidx;
    }
}

// ============ Kernel 3: mean -> thr5, then per-window validity bits =========
// One block per channel. Phase 1: deterministic sum -> thr. Phase 2: scan this
// channel's contiguous gMaxVal/gMaxIdx and atomicOr validity bits into gValid
// (bitwise OR is order-independent -> deterministic).
//  M <= thr          -> contributes nothing
//  M >  thr, M > 0   -> bit0 if first index of max == 128
//  M >  thr, M <= 0  -> bit1 (patch does exact rescan; measure-zero case)
__global__ void mean_kernel() {
    __shared__ float sh[128];
    __shared__ float sThr;
    int c = blockIdx.x;
    int tid = threadIdx.x;
    float s = 0.0f;
    for (int i = tid; i < NWIN; i += 128) s += gPartial[c * NWIN + i];
    sh[tid] = s;
    __syncthreads();
    if (tid < 64) sh[tid] += sh[tid + 64];
    __syncthreads();
    if (tid < 32) {
        s = sh[tid] + sh[tid + 32];
        #pragma unroll
        for (int off = 16; off; off >>= 1)
            s += __shfl_down_sync(0xffffffffu, s, off);
        if (tid == 0) {
            float thr = (s / (float)(HH * WW)) * 5.0f;
            gThr5[c] = thr;
            sThr = thr;
        }
    }
    __syncthreads();
    float thr = sThr;
    for (int i = tid; i < NWIN; i += 128) {
        float M  = gMaxVal[c * NWIN + i];
        int   id = gMaxIdx[c * NWIN + i];
        if (M > thr) {
            int bits = (M > 0.0f) ? ((id == 128) ? 1 : 0) : 2;
            if (bits) atomicOr(&gValid[i], bits);
        }
    }
}

// ============ Kernel 4: patches — zero fast path for invalid windows ========
// 961 blocks x 256 threads, all 9 channels per block.
// mask[c] = valid_kp[w] && nonzero(patch). valid_kp is true for only a
// handful of windows, so ~99.5% of blocks take the NO-READ path: stream
// 9 float4 zero-stores per thread (output is zero by construction).
// Valid blocks (rare) do the exact nz-mask pass + masked-store pass.
__global__ void __launch_bounds__(256)
patch_kernel(float* __restrict__ dst) {
    __shared__ unsigned sW[8];
    __shared__ float sRv[NC][8];
    __shared__ int   sRi[NC][8];
    __shared__ int   sValid;

    int w = blockIdx.x;
    int tid = threadIdx.x;
    int lane = tid & 31, wid = tid >> 5;

    int vf = gValid[w];
    int valid;
    if (vf & 2) {                  // exact rescan, block-uniform, rare
        int R = (w / NW) * 16, C = (w % NW) * 16;
        int fi = tid >> 4, fj = tid & 15;          // f == tid, ascending
        for (int ch = 0; ch < NC; ch++) {
            float thr = gThr5[ch];
            float v = gOut[ch * HH * WW + (R + fi) * WW + C + fj];
            float best = (v > thr) ? v : 0.0f;
            int bidx = tid;
            #pragma unroll
            for (int off = 16; off; off >>= 1) {
                float ov = __shfl_xor_sync(0xffffffffu, best, off);
                int   oi = __shfl_xor_sync(0xffffffffu, bidx, off);
                if (ov > best || (ov == best && oi < bidx)) { best = ov; bidx = oi; }
            }
            if (lane == 0) { sRv[ch][wid] = best; sRi[ch][wid] = bidx; }
        }
        __syncthreads();
        if (tid == 0) {
            int vv = 0;
            for (int ch = 0; ch < NC; ch++) {
                float best = sRv[ch][0]; int bidx = sRi[ch][0];
                for (int k = 1; k < 8; k++) {
                    float ov = sRv[ch][k]; int oi = sRi[ch][k];
                    if (ov > best || (ov == best && oi < bidx)) { best = ov; bidx = oi; }
                }
                vv |= (bidx == 128);
            }
            sValid = vv;
        }
        __syncthreads();
        valid = sValid;
    } else {
        valid = vf & 1;
    }

    // ---- fast path: invalid window -> pure zero stores, no reads ----
    if (!valid) {
        float4 z = make_float4(0.0f, 0.0f, 0.0f, 0.0f);
        #pragma unroll
        for (int c = 0; c < NC; c++)
            ((float4*)dst)[(c * NWIN + w) * 256 + tid] = z;
        return;
    }

    // ---- rare path: valid window, exact nz mask + masked store ----
    int wr = (w / NW) * 16 - 8;    // top row of 32x32 patch in image coords
    int wc = (w % NW) * 16 - 8;
    int i  = tid >> 3;             // patch row 0..31
    int j0 = (tid & 7) * 4;        // patch col base
    int rr = wr + i;
    bool interior = (wr >= 0) & (wr + 31 < HH) & (wc >= 0) & (wc + 31 < WW);
    bool rok = (rr >= 0 && rr < HH);

    unsigned nzm = 0;
    if (interior) {
        const float* base = gOut + rr * WW + wc + j0;
        #pragma unroll
        for (int c = 0; c < NC; c++) {
            float4 v = *(const float4*)(base + c * HH * WW);
            if ((v.x != 0.0f) | (v.y != 0.0f) | (v.z != 0.0f) | (v.w != 0.0f))
                nzm |= 1u << c;
        }
    } else {
        #pragma unroll
        for (int c = 0; c < NC; c++) {
            const float* o = gOut + c * HH * WW;
            bool nz = false;
            #pragma unroll
            for (int e = 0; e < 4; e++) {
                int cc = wc + j0 + e;
                float t = (rok && cc >= 0 && cc < WW) ? o[rr * WW + cc] : 0.0f;
                nz |= (t != 0.0f);
            }
            if (nz) nzm |= 1u << c;
        }
    }
    unsigned wm = __reduce_or_sync(0xffffffffu, nzm);
    if (lane == 0) sW[wid] = wm;
    __syncthreads();
    unsigned blockmask = 0;
    #pragma unroll
    for (int k = 0; k < 8; k++) blockmask |= sW[k];

    if (interior) {
        const float* base = gOut + rr * WW + wc + j0;
        #pragma unroll
        for (int c = 0; c < NC; c++) {
            float m = ((blockmask >> c) & 1u) ? 1.0f : 0.0f;
            float4 v = *(const float4*)(base + c * HH * WW);
            float4 ov = make_float4(v.x * m, v.y * m, v.z * m, v.w * m);
            ((float4*)dst)[(c * NWIN + w) * 256 + tid] = ov;
        }
    } else {
        #pragma unroll
        for (int c = 0; c < NC; c++) {
            float m = ((blockmask >> c) & 1u) ? 1.0f : 0.0f;
            const float* o = gOut + c * HH * WW;
            float t[4];
            #pragma unroll
            for (int e = 0; e < 4; e++) {
                int cc = wc + j0 + e;
                t[e] = (rok && cc >= 0 && cc < WW) ? o[rr * WW + cc] : 0.0f;
            }
            float4 ov = make_float4(t[0] * m, t[1] * m, t[2] * m, t[3] * m);
            ((float4*)dst)[(c * NWIN + w) * 256 + tid] = ov;
        }
    }
}

// ============ launcher ============
extern "C" void kernel_launch(void* const* d_in, const int* in_sizes, int n_in,
                              void* d_out, int out_size) {
    const float* img     = (const float*)d_in[0];
    const float* sigmas  = (const float*)d_in[1];
    const float* lambdas = (const float*)d_in[2];
    float* out = (float*)d_out;

    gabor_kernel<<<(NCOEF + 255) / 256, 256>>>(sigmas, lambdas);
    conv_kernel<<<dim3(NW, NW), 64>>>(img);
    mean_kernel<<<NC, 128>>>();
    patch_kernel<<<NWIN, 256>>>(out);
}

// round 17
// speedup vs baseline: 1.0883x; 1.0322x over previous
#include <cuda_runtime.h>
#include <math.h>
#include <float.h>

#define HH 496
#define WW 496
#define NC 9          // sigma x lambda combos
#define NT 8          // thetas
#define NW 31         // windows per dim (496/16)
#define NWIN (NW*NW)  // 961
#define NCOEF (NT*NC*25)
#define NFILT (NT*NC)

// ---- scratch (static device globals; no allocation) ----
__device__ float gCoef[NCOEF];                // [t][c][25] dense
__device__ float gOut[NC*HH*WW];              // conv+max result, 8.86 MB
__device__ float gPartial[NC*NWIN];           // per-window channel sums
__device__ float gMaxVal[NC*NWIN];            // per-window channel max
__device__ int   gMaxIdx[NC*NWIN];            // first index of max (0..255)
__device__ float gThr5[NC];                   // mean*5 per channel
__device__ int   gValid[NWIN];                // bit0: valid, bit1: needs exact rescan

__device__ __constant__ float dThetas[8] = {
    0.39269908169872414f, 0.7853981633974483f, 1.1780972450961724f,
    1.5707963267948966f,  1.9634954084936207f, 2.356194490192345f,
    2.748893571891069f,   3.141592653589793f
};

// ============ Kernel 1: Gabor bank ============
__global__ void gabor_kernel(const float* __restrict__ sigmas,
                             const float* __restrict__ lambdas) {
    int i = blockIdx.x * blockDim.x + threadIdx.x;
    if (i >= NCOEF) return;
    int k = i % 25;
    int c = (i / 25) % NC;
    int t = i / (25 * NC);
    int s = c / 3, l = c % 3;
    float sig = sigmas[s];
    float lam = lambdas[l];
    float th  = dThetas[t];
    int ky = k / 5, kx = k % 5;
    float y = (float)ky - 2.0f;
    float x = (float)kx - 2.0f;
    float st = sinf(th), ct = cosf(th);
    float yth = -x * st + y * ct;
    float xth =  x * ct + y * st;
    float sx = sig;          // sigma_x
    float sy = 2.0f * sig;   // sigma_y = sigma/gamma, gamma=0.5
    float e = expf(-0.5f * (xth*xth/(sx*sx) + yth*yth/(sy*sy)));
    float g = e * cosf(6.283185307179586f * xth / lam + 1.5707963267948966f);
    gCoef[(t * NC + c) * 25 + k] = g;
}

// ============ Kernel 2: conv (scalar FFMA, proven) + fused window stats =====
// 31x31 blocks of 64 threads; 16x16 output tile == one detection window.
// Thread = 4 horizontal pixels; per coefficient 1 smem load feeds 4 FMAs.
// Coefficient rows padded to 28 floats (112B) so taps load as LDS.128 x6 + 1.
__global__ void __launch_bounds__(64)
conv_kernel(const float* __restrict__ img) {
    __shared__ float sIn[20 * 20];
    __shared__ float sCf[NFILT * 28];   // padded: row f at 28*f, 16B-aligned
    __shared__ float sVal[NC][2];
    __shared__ int   sIdx[NC][2];
    __shared__ float sSum[NC][2];

    int tid = threadIdx.x;
    int bx = blockIdx.x, by = blockIdx.y;
    int r0 = by * 16 - 2, c0 = bx * 16 - 2;

    // reset validity accumulator for this window (graph replays stay pure)
    if (tid == 32) gValid[by * NW + bx] = 0;

    // halo'd input tile (zero pad)
    for (int i = tid; i < 400; i += 64) {
        int r = i / 20, cc = i % 20;
        int gr = r0 + r, gc = c0 + cc;
        sIn[i] = (gr >= 0 && gr < HH && gc >= 0 && gc < WW) ? img[gr * WW + gc] : 0.0f;
    }
    // coefficients -> padded smem rows
    for (int i = tid; i < NCOEF; i += 64) {
        int f = i / 25, k = i % 25;
        sCf[f * 28 + k] = gCoef[i];
    }
    __syncthreads();

    int ty = tid >> 2;            // 0..15
    int tx = (tid & 3) * 4;       // 0,4,8,12

    float vin[5][8];
    #pragma unroll
    for (int r = 0; r < 5; r++)
        #pragma unroll
        for (int cc = 0; cc < 8; cc++)
            vin[r][cc] = sIn[(ty + r) * 20 + tx + cc];

    float vmax[4][NC];
    #pragma unroll
    for (int p = 0; p < 4; p++)
        #pragma unroll
        for (int c = 0; c < NC; c++) vmax[p][c] = -FLT_MAX;

#define TAP(wv, kk) { const int ky = (kk) / 5, kx = (kk) % 5;                 \
        a0 = fmaf((wv), vin[ky][kx + 0], a0);                                 \
        a1 = fmaf((wv), vin[ky][kx + 1], a1);                                 \
        a2 = fmaf((wv), vin[ky][kx + 2], a2);                                 \
        a3 = fmaf((wv), vin[ky][kx + 3], a3); }

    for (int t = 0; t < NT; t++) {
        #pragma unroll
        for (int c = 0; c < NC; c++) {
            const float* cf = sCf + (t * NC + c) * 28;
            const float4* cf4 = (const float4*)cf;
            float a0 = 0.0f, a1 = 0.0f, a2 = 0.0f, a3 = 0.0f;
            #pragma unroll
            for (int q = 0; q < 6; q++) {
                float4 w = cf4[q];
                TAP(w.x, 4 * q + 0)
                TAP(w.y, 4 * q + 1)
                TAP(w.z, 4 * q + 2)
                TAP(w.w, 4 * q + 3)
            }
            float w24 = cf[24];
            TAP(w24, 24)
            vmax[0][c] = fmaxf(vmax[0][c], a0);
            vmax[1][c] = fmaxf(vmax[1][c], a1);
            vmax[2][c] = fmaxf(vmax[2][c], a2);
            vmax[3][c] = fmaxf(vmax[3][c], a3);
        }
    }
#undef TAP

    // global stores
    int gy = by * 16 + ty;
    int gx = bx * 16 + tx;
    #pragma unroll
    for (int c = 0; c < NC; c++) {
        float4 o = make_float4(vmax[0][c], vmax[1][c], vmax[2][c], vmax[3][c]);
        *(float4*)&gOut[c * HH * WW + gy * WW + gx] = o;
    }

    // fused per-window stats. Flat index within 16x16 for element e of this
    // thread is exactly f = 4*tid + e (ascending), so first-occurrence
    // argmax = min-index tie-breaking across lanes.
    int lane = tid & 31, wid = tid >> 5;
    #pragma unroll
    for (int c = 0; c < NC; c++) {
        float best = vmax[0][c]; int bidx = 4 * tid;
        if (vmax[1][c] > best) { best = vmax[1][c]; bidx = 4 * tid + 1; }
        if (vmax[2][c] > best) { best = vmax[2][c]; bidx = 4 * tid + 2; }
        if (vmax[3][c] > best) { best = vmax[3][c]; bidx = 4 * tid + 3; }
        float s = vmax[0][c] + vmax[1][c] + vmax[2][c] + vmax[3][c];
        #pragma unroll
        for (int off = 16; off; off >>= 1) {
            s += __shfl_xor_sync(0xffffffffu, s, off);
            float ov = __shfl_xor_sync(0xffffffffu, best, off);
            int   oi = __shfl_xor_sync(0xffffffffu, bidx, off);
            if (ov > best || (ov == best && oi < bidx)) { best = ov; bidx = oi; }
        }
        if (lane == 0) { sVal[c][wid] = best; sIdx[c][wid] = bidx; sSum[c][wid] = s; }
    }
    __syncthreads();
    if (tid < NC) {
        float best = sVal[tid][0]; int bidx = sIdx[tid][0];
        float s = sSum[tid][0] + sSum[tid][1];
        float ov = sVal[tid][1]; int oi = sIdx[tid][1];
        if (ov > best || (ov == best && oi < bidx)) { best = ov; bidx = oi; }
        int b = by * NW + bx;
        gPartial[tid * NWIN + b] = s;
        gMaxVal[tid * NWIN + b]  = best;
        gMaxIdx[tid * NWIN + b]  = bidx;
    }
}

// ============ Kernel 3: mean -> thr5, then per-window validity bits =========
// One block per channel. Phase 1: deterministic sum -> thr. Phase 2: scan this
// channel's contiguous gMaxVal/gMaxIdx and atomicOr validity bits into gValid
// (bitwise OR is order-independent -> deterministic).
//  M <= thr          -> contributes nothing
//  M >  thr, M > 0   -> bit0 if first index of max == 128
//  M >  thr, M <= 0  -> bit1 (patch does exact rescan; measure-zero case)
__global__ void mean_kernel() {
    __shared__ float sh[128];
    __shared__ float sThr;
    int c = blockIdx.x;
    int tid = threadIdx.x;
    float s = 0.0f;
    for (int i = tid; i < NWIN; i += 128) s += gPartial[c * NWIN + i];
    sh[tid] = s;
    __syncthreads();
    if (tid < 64) sh[tid] += sh[tid + 64];
    __syncthreads();
    if (tid < 32) {
        s = sh[tid] + sh[tid + 32];
        #pragma unroll
        for (int off = 16; off; off >>= 1)
            s += __shfl_down_sync(0xffffffffu, s, off);
        if (tid == 0) {
            float thr = (s / (float)(HH * WW)) * 5.0f;
            gThr5[c] = thr;
            sThr = thr;
        }
    }
    __syncthreads();
    float thr = sThr;
    for (int i = tid; i < NWIN; i += 128) {
        float M  = gMaxVal[c * NWIN + i];
        int   id = gMaxIdx[c * NWIN + i];
        if (M > thr) {
            int bits = (M > 0.0f) ? ((id == 128) ? 1 : 0) : 2;
            if (bits) atomicOr(&gValid[i], bits);
        }
    }
}

// ============ Kernel 4: patches — grid (961, 3), 3 channels per block ========
// 2883 blocks x 256 threads (~2.4 waves) so block-start gValid latency chains
// overlap across waves. mask[c] = valid_kp[w] && nonzero(patch_c) is per-channel
// independent, so a block can own channels 3*by..3*by+2 outright.
// ~99.5% of blocks take the NO-READ zero-store path (3 STG.128/thread).
__global__ void __launch_bounds__(256)
patch_kernel(float* __restrict__ dst) {
    __shared__ unsigned sW[8];
    __shared__ float sRv[NC][8];
    __shared__ int   sRi[NC][8];
    __shared__ int   sValid;

    int w = blockIdx.x;
    int vf = __ldg(&gValid[w]);            // hoisted: single dependent load
    int cb = blockIdx.y * 3;               // first channel of this block
    int tid = threadIdx.x;
    int lane = tid & 31, wid = tid >> 5;

    int valid;
    if (vf & 2) {                  // exact rescan, block-uniform, rare
        int R = (w / NW) * 16, C = (w % NW) * 16;
        int fi = tid >> 4, fj = tid & 15;          // f == tid, ascending
        for (int ch = 0; ch < NC; ch++) {
            float thr = gThr5[ch];
            float v = gOut[ch * HH * WW + (R + fi) * WW + C + fj];
            float best = (v > thr) ? v : 0.0f;
            int bidx = tid;
            #pragma unroll
            for (int off = 16; off; off >>= 1) {
                float ov = __shfl_xor_sync(0xffffffffu, best, off);
                int   oi = __shfl_xor_sync(0xffffffffu, bidx, off);
                if (ov > best || (ov == best && oi < bidx)) { best = ov; bidx = oi; }
            }
            if (lane == 0) { sRv[ch][wid] = best; sRi[ch][wid] = bidx; }
        }
        __syncthreads();
        if (tid == 0) {
            int vv = 0;
            for (int ch = 0; ch < NC; ch++) {
                float best = sRv[ch][0]; int bidx = sRi[ch][0];
                for (int k = 1; k < 8; k++) {
                    float ov = sRv[ch][k]; int oi = sRi[ch][k];
                    if (ov > best || (ov == best && oi < bidx)) { best = ov; bidx = oi; }
                }
                vv |= (bidx == 128);
            }
            sValid = vv;
        }
        __syncthreads();
        valid = sValid;
    } else {
        valid = vf & 1;
    }

    // ---- fast path: invalid window -> pure zero stores, no reads ----
    if (!valid) {
        float4 z = make_float4(0.0f, 0.0f, 0.0f, 0.0f);
        #pragma unroll
        for (int q = 0; q < 3; q++)
            ((float4*)dst)[((cb + q) * NWIN + w) * 256 + tid] = z;
        return;
    }

    // ---- rare path: valid window, exact nz mask + masked store (3 ch) ----
    int wr = (w / NW) * 16 - 8;    // top row of 32x32 patch in image coords
    int wc = (w % NW) * 16 - 8;
    int i  = tid >> 3;             // patch row 0..31
    int j0 = (tid & 7) * 4;        // patch col base
    int rr = wr + i;
    bool interior = (wr >= 0) & (wr + 31 < HH) & (wc >= 0) & (wc + 31 < WW);
    bool rok = (rr >= 0 && rr < HH);

    unsigned nzm = 0;
    if (interior) {
        const float* base = gOut + rr * WW + wc + j0;
        #pragma unroll
        for (int q = 0; q < 3; q++) {
            float4 v = *(const float4*)(base + (cb + q) * HH * WW);
            if ((v.x != 0.0f) | (v.y != 0.0f) | (v.z != 0.0f) | (v.w != 0.0f))
                nzm |= 1u << q;
        }
    } else {
        #pragma unroll
        for (int q = 0; q < 3; q++) {
            const float* o = gOut + (cb + q) * HH * WW;
            bool nz = false;
            #pragma unroll
            for (int e = 0; e < 4; e++) {
                int cc = wc + j0 + e;
                float t = (rok && cc >= 0 && cc < WW) ? o[rr * WW + cc] : 0.0f;
                nz |= (t != 0.0f);
            }
            if (nz) nzm |= 1u << q;
        }
    }
    unsigned wm = __reduce_or_sync(0xffffffffu, nzm);
    if (lane == 0) sW[wid] = wm;
    __syncthreads();
    unsigned blockmask = 0;
    #pragma unroll
    for (int k = 0; k < 8; k++) blockmask |= sW[k];

    if (interior) {
        const float* base = gOut + rr * WW + wc + j0;
        #pragma unroll
        for (int q = 0; q < 3; q++) {
            float m = ((blockmask >> q) & 1u) ? 1.0f : 0.0f;
            float4 v = *(const float4*)(base + (cb + q) * HH * WW);
            float4 ov = make_float4(v.x * m, v.y * m, v.z * m, v.w * m);
            ((float4*)dst)[((cb + q) * NWIN + w) * 256 + tid] = ov;
        }
    } else {
        #pragma unroll
        for (int q = 0; q < 3; q++) {
            float m = ((blockmask >> q) & 1u) ? 1.0f : 0.0f;
            const float* o = gOut + (cb + q) * HH * WW;
            float t[4];
            #pragma unroll
            for (int e = 0; e < 4; e++) {
                int cc = wc + j0 + e;
                t[e] = (rok && cc >= 0 && cc < WW) ? o[rr * WW + cc] : 0.0f;
            }
            float4 ov = make_float4(t[0] * m, t[1] * m, t[2] * m, t[3] * m);
            ((float4*)dst)[((cb + q) * NWIN + w) * 256 + tid] = ov;
        }
    }
}

// ============ launcher ============
extern "C" void kernel_launch(void* const* d_in, const int* in_sizes, int n_in,
                              void* d_out, int out_size) {
    const float* img     = (const float*)d_in[0];
    const float* sigmas  = (const float*)d_in[1];
    const float* lambdas = (const float*)d_in[2];
    float* out = (float*)d_out;

    gabor_kernel<<<(NCOEF + 255) / 256, 256>>>(sigmas, lambdas);
    conv_kernel<<<dim3(NW, NW), 64>>>(img);
    mean_kernel<<<NC, 128>>>();
    patch_kernel<<<dim3(NWIN, 3), 256>>>(out);
}